// round 11
// baseline (speedup 1.0000x reference)
#include <cuda_runtime.h>
#include <cuda_fp16.h>
#include <cstdint>

#define MAX_NODES 100000
#define D 128
#define EPT 7           // edges per thread (edge kernels)
#define EBLK 1024       // threads per block (edge kernels)

#define TABLE_BYTES (MAX_NODES * 2)      // one fp16 table = 200000 B
#define SMEM_TABLE_OFF 16                // mbarrier at 0, table at 16
#define SMEM_TOTAL (SMEM_TABLE_OFF + TABLE_BYTES)

// Per-node projections, both fp16. Bias folded into d at the node pass.
__device__ __align__(16) __half g_s_h[MAX_NODES];
__device__ __align__(16) __half g_d_h[MAX_NODES];

__device__ __forceinline__ uint32_t smem_u32(const void* p) {
    uint32_t a;
    asm("{ .reg .u64 t; cvta.to.shared.u64 t, %1; cvt.u32.u64 %0, t; }" : "=r"(a) : "l"(p));
    return a;
}

__device__ __forceinline__ float sigmoidf_fast(float z) {
    return 1.0f / (1.0f + __expf(-z));
}

// Kernel 1: 4 nodes per warp via 8-lane subgroups (6 SHFL per 4 nodes).
__global__ void node_dots_kernel(const float4* __restrict__ x4,
                                 const float* __restrict__ W,
                                 const float* __restrict__ b,
                                 int n_nodes) {
    __shared__ float4 ws4[32];
    __shared__ float4 wd4[32];
    int tid = threadIdx.x;
    if (tid < 32) ws4[tid] = ((const float4*)W)[tid];
    else if (tid < 64) wd4[tid - 32] = ((const float4*)W)[tid - 32 + 32];
    __syncthreads();

    int lane = tid & 31;
    int g    = lane & 7;
    int sub  = lane >> 3;
    int warpId = (blockIdx.x * blockDim.x + tid) >> 5;
    int node = warpId * 4 + sub;
    if (node >= n_nodes) return;

    const float4* row = x4 + (size_t)node * 32;
    float s = 0.f, d = 0.f;
    #pragma unroll
    for (int it = 0; it < 4; it++) {
        float4 v = row[it * 8 + g];
        float4 a = ws4[it * 8 + g];
        float4 c = wd4[it * 8 + g];
        s += v.x * a.x + v.y * a.y + v.z * a.z + v.w * a.w;
        d += v.x * c.x + v.y * c.y + v.z * c.z + v.w * c.w;
    }
    #pragma unroll
    for (int off = 4; off > 0; off >>= 1) {
        s += __shfl_down_sync(0xFFFFFFFFu, s, off);
        d += __shfl_down_sync(0xFFFFFFFFu, d, off);
    }
    if (g == 0) {
        float b0 = __ldg(b);
        g_s_h[node] = __float2half(s);
        g_d_h[node] = __float2half(d + b0);
    }
}

// Shared pattern: one TMA bulk copy of a 200KB fp16 table into smem,
// overlapped with coalesced index (+ optional partial) streaming; one
// mbarrier wait; LDS gathers; coalesced stores. Two instances below,
// each with exactly ONE broadcast -> no mid-kernel dead window.

// Kernel 2a: partial[e] = s_table[src[e]] (widened to fp32, lossless)
__global__ void __launch_bounds__(EBLK, 1)
edge_s_kernel(const int* __restrict__ src,
              float* __restrict__ out,   // holds partial logits
              int n_edges) {
    extern __shared__ char smem_raw[];
    __half* tab = reinterpret_cast<__half*>(smem_raw + SMEM_TABLE_OFF);
    uint32_t mbar = smem_u32(smem_raw);

    int tid = threadIdx.x;
    if (tid == 0)
        asm volatile("mbarrier.init.shared.b64 [%0], 1;" :: "r"(mbar) : "memory");
    __syncthreads();
    if (tid == 0) {
        asm volatile("mbarrier.arrive.expect_tx.shared.b64 _, [%0], %1;"
                     :: "r"(mbar), "r"((uint32_t)TABLE_BYTES) : "memory");
        asm volatile(
            "cp.async.bulk.shared::cta.global.mbarrier::complete_tx::bytes [%0], [%1], %2, [%3];"
            :: "r"(smem_u32(tab)), "l"((const void*)g_s_h),
               "r"((uint32_t)TABLE_BYTES), "r"(mbar) : "memory");
    }

    int gtid = blockIdx.x * EBLK + tid;
    int stride = gridDim.x * EBLK;

    int si[EPT];
    #pragma unroll
    for (int k = 0; k < EPT; k++) {
        int e = gtid + k * stride;
        si[k] = (e < n_edges) ? __ldcs(src + e) : 0;
    }

    asm volatile(
        "{\n\t.reg .pred P;\n\t"
        "W_%=:\n\t"
        "mbarrier.try_wait.parity.acquire.cta.shared::cta.b64 P, [%0], 0, 0x989680;\n\t"
        "@!P bra W_%=;\n\t}"
        :: "r"(mbar) : "memory");

    #pragma unroll
    for (int k = 0; k < EPT; k++) {
        int e = gtid + k * stride;
        if (e < n_edges)
            __stcs(out + e, __half2float(tab[si[k]]));
    }
}

// Kernel 2b: out[e] = sigmoid(partial[e] + d_table[dst[e]])
__global__ void __launch_bounds__(EBLK, 1)
edge_d_kernel(const int* __restrict__ dst,
              float* __restrict__ out,
              int n_edges) {
    extern __shared__ char smem_raw[];
    __half* tab = reinterpret_cast<__half*>(smem_raw + SMEM_TABLE_OFF);
    uint32_t mbar = smem_u32(smem_raw);

    int tid = threadIdx.x;
    if (tid == 0)
        asm volatile("mbarrier.init.shared.b64 [%0], 1;" :: "r"(mbar) : "memory");
    __syncthreads();
    if (tid == 0) {
        asm volatile("mbarrier.arrive.expect_tx.shared.b64 _, [%0], %1;"
                     :: "r"(mbar), "r"((uint32_t)TABLE_BYTES) : "memory");
        asm volatile(
            "cp.async.bulk.shared::cta.global.mbarrier::complete_tx::bytes [%0], [%1], %2, [%3];"
            :: "r"(smem_u32(tab)), "l"((const void*)g_d_h),
               "r"((uint32_t)TABLE_BYTES), "r"(mbar) : "memory");
    }

    int gtid = blockIdx.x * EBLK + tid;
    int stride = gridDim.x * EBLK;

    int   di[EPT];
    float ph[EPT];
    #pragma unroll
    for (int k = 0; k < EPT; k++) {
        int e = gtid + k * stride;
        bool ok = e < n_edges;
        di[k] = ok ? __ldcs(dst + e) : 0;
        ph[k] = ok ? __ldcs(out + e) : 0.f;
    }

    asm volatile(
        "{\n\t.reg .pred P;\n\t"
        "W_%=:\n\t"
        "mbarrier.try_wait.parity.acquire.cta.shared::cta.b64 P, [%0], 0, 0x989680;\n\t"
        "@!P bra W_%=;\n\t}"
        :: "r"(mbar) : "memory");

    #pragma unroll
    for (int k = 0; k < EPT; k++) {
        int e = gtid + k * stride;
        if (e < n_edges)
            __stcs(out + e, sigmoidf_fast(ph[k] + __half2float(tab[di[k]])));
    }
}

extern "C" void kernel_launch(void* const* d_in, const int* in_sizes, int n_in,
                              void* d_out, int out_size) {
    const float* x   = (const float*)d_in[0];
    const int*   src = (const int*)d_in[1];
    const int*   dst = (const int*)d_in[2];
    const float* W   = (const float*)d_in[3];
    const float* b   = (const float*)d_in[4];
    float*       out = (float*)d_out;

    int n_nodes = in_sizes[0] / D;
    int n_edges = in_sizes[1];

    // Kernel 1: 4 nodes per warp, 8 warps/block -> 32 nodes/block
    {
        int nodes_per_block = 8 * 4;
        int blocks = (n_nodes + nodes_per_block - 1) / nodes_per_block;
        node_dots_kernel<<<blocks, 256>>>((const float4*)x, W, b, n_nodes);
    }
    // Kernels 2a/2b: single-broadcast table gathers, full-chip grids
    {
        static bool attr_set = false;
        if (!attr_set) {
            cudaFuncSetAttribute(edge_s_kernel,
                                 cudaFuncAttributeMaxDynamicSharedMemorySize, SMEM_TOTAL);
            cudaFuncSetAttribute(edge_d_kernel,
                                 cudaFuncAttributeMaxDynamicSharedMemorySize, SMEM_TOTAL);
            attr_set = true;
        }
        long long per_blk = (long long)EBLK * EPT;
        int blocks = (int)((n_edges + per_blk - 1) / per_blk);  // 140 for 1e6
        edge_s_kernel<<<blocks, EBLK, SMEM_TOTAL>>>(src, out, n_edges);
        edge_d_kernel<<<blocks, EBLK, SMEM_TOTAL>>>(dst, out, n_edges);
    }
}

// round 12
// speedup vs baseline: 1.2224x; 1.2224x over previous
#include <cuda_runtime.h>
#include <cuda_fp16.h>
#include <cstdint>

#define MAX_NODES 100000
#define D 128
#define EPT 7           // edges per thread (edge kernel)
#define EBLK 1024       // threads per block (edge kernel)

#define TABLE_BYTES (MAX_NODES * 2)      // one fp16 table = 200000 B
#define SMEM_TABLE_OFF 16                // mbarrier at 0, table at 16
#define SMEM_TOTAL (SMEM_TABLE_OFF + TABLE_BYTES)

// Per-node projections, both fp16. Bias folded into d at the node pass.
__device__ __align__(16) __half g_s_h[MAX_NODES];
__device__ __align__(16) __half g_d_h[MAX_NODES];

__device__ __forceinline__ uint32_t smem_u32(const void* p) {
    uint32_t a;
    asm("{ .reg .u64 t; cvta.to.shared.u64 t, %1; cvt.u32.u64 %0, t; }" : "=r"(a) : "l"(p));
    return a;
}

__device__ __forceinline__ float sigmoidf_fast(float z) {
    return 1.0f / (1.0f + __expf(-z));
}

// Kernel 1: 8 nodes per warp via 8-lane subgroups, 2 nodes per thread.
// All 8 LDG.128 issued up-front (MLP=8 per thread), weight chunks reused
// across the two rows, 12 SHFL per 8 nodes (1.5/node).
__global__ void node_dots_kernel(const float4* __restrict__ x4,
                                 const float* __restrict__ W,
                                 const float* __restrict__ b,
                                 int n_nodes) {
    __shared__ float4 ws4[32];
    __shared__ float4 wd4[32];
    int tid = threadIdx.x;
    if (tid < 32) ws4[tid] = ((const float4*)W)[tid];
    else if (tid < 64) wd4[tid - 32] = ((const float4*)W)[tid - 32 + 32];
    __syncthreads();

    int lane = tid & 31;
    int g    = lane & 7;     // position within 8-lane group
    int sub  = lane >> 3;    // subgroup id 0..3
    int warpId = (blockIdx.x * blockDim.x + tid) >> 5;
    int base = warpId * 8;
    int nodeA = base + sub;
    int nodeB = base + 4 + sub;
    if (nodeA >= n_nodes) return;
    bool hasB = nodeB < n_nodes;

    const float4* rowA = x4 + (size_t)nodeA * 32;
    const float4* rowB = x4 + (size_t)nodeB * 32;

    // All 8 loads up-front
    float4 va[4], vb[4];
    #pragma unroll
    for (int it = 0; it < 4; it++) va[it] = rowA[it * 8 + g];
    #pragma unroll
    for (int it = 0; it < 4; it++)
        vb[it] = hasB ? rowB[it * 8 + g] : make_float4(0.f, 0.f, 0.f, 0.f);

    float sA = 0.f, dA = 0.f, sB = 0.f, dB = 0.f;
    #pragma unroll
    for (int it = 0; it < 4; it++) {
        float4 a = ws4[it * 8 + g];
        float4 c = wd4[it * 8 + g];
        sA += va[it].x * a.x + va[it].y * a.y + va[it].z * a.z + va[it].w * a.w;
        dA += va[it].x * c.x + va[it].y * c.y + va[it].z * c.z + va[it].w * c.w;
        sB += vb[it].x * a.x + vb[it].y * a.y + vb[it].z * a.z + vb[it].w * a.w;
        dB += vb[it].x * c.x + vb[it].y * c.y + vb[it].z * c.z + vb[it].w * c.w;
    }

    // 3-round reduction within each 8-lane group (4 values at once)
    #pragma unroll
    for (int off = 4; off > 0; off >>= 1) {
        sA += __shfl_down_sync(0xFFFFFFFFu, sA, off);
        dA += __shfl_down_sync(0xFFFFFFFFu, dA, off);
        sB += __shfl_down_sync(0xFFFFFFFFu, sB, off);
        dB += __shfl_down_sync(0xFFFFFFFFu, dB, off);
    }
    if (g == 0) {
        float b0 = __ldg(b);
        g_s_h[nodeA] = __float2half(sA);
        g_d_h[nodeA] = __float2half(dA + b0);
        if (hasB) {
            g_s_h[nodeB] = __float2half(sB);
            g_d_h[nodeB] = __float2half(dB + b0);
        }
    }
}

// Kernel 2: table-swap edge scoring (R9 config: grid ~140, EPT=7).
// One 200KB smem buffer filled twice by TMA bulk copies (async proxy,
// no L1tex work): s-table (LDS-gather s into registers), then d-table
// (LDS-gather d, sigmoid, store). All 2e6 gathers are LDS.
__global__ void __launch_bounds__(EBLK, 1)
edge_score_swap_kernel(const int* __restrict__ src,
                       const int* __restrict__ dst,
                       float* __restrict__ out,
                       int n_edges) {
    extern __shared__ char smem_raw[];
    __half* tab = reinterpret_cast<__half*>(smem_raw + SMEM_TABLE_OFF);
    uint32_t mbar = smem_u32(smem_raw);
    uint32_t tab_a = smem_u32(tab);

    int tid = threadIdx.x;

    if (tid == 0) {
        asm volatile("mbarrier.init.shared.b64 [%0], 1;" :: "r"(mbar) : "memory");
    }
    __syncthreads();
    // Broadcast 1: s-table
    if (tid == 0) {
        asm volatile("mbarrier.arrive.expect_tx.shared.b64 _, [%0], %1;"
                     :: "r"(mbar), "r"((uint32_t)TABLE_BYTES) : "memory");
        asm volatile(
            "cp.async.bulk.shared::cta.global.mbarrier::complete_tx::bytes [%0], [%1], %2, [%3];"
            :: "r"(tab_a), "l"((const void*)g_s_h),
               "r"((uint32_t)TABLE_BYTES), "r"(mbar) : "memory");
    }

    int gtid = blockIdx.x * EBLK + tid;
    int stride = gridDim.x * EBLK;

    // Index loads in flight while broadcast 1 flies.
    int si[EPT], di[EPT];
    #pragma unroll
    for (int k = 0; k < EPT; k++) {
        int e = gtid + k * stride;
        bool ok = e < n_edges;
        si[k] = ok ? __ldcs(src + e) : 0;
        di[k] = ok ? __ldcs(dst + e) : 0;
    }

    // Wait table 1 (phase parity 0)
    asm volatile(
        "{\n\t.reg .pred P;\n\t"
        "W0_%=:\n\t"
        "mbarrier.try_wait.parity.acquire.cta.shared::cta.b64 P, [%0], 0, 0x989680;\n\t"
        "@!P bra W0_%=;\n\t}"
        :: "r"(mbar) : "memory");

    float part[EPT];
    #pragma unroll
    for (int k = 0; k < EPT; k++)
        part[k] = __half2float(tab[si[k]]);

    // All phase-S reads done before the buffer is overwritten.
    __syncthreads();
    // Broadcast 2: d-table (generic->async proxy ordering via fence)
    if (tid == 0) {
        asm volatile("fence.proxy.async.shared::cta;" ::: "memory");
        asm volatile("mbarrier.arrive.expect_tx.shared.b64 _, [%0], %1;"
                     :: "r"(mbar), "r"((uint32_t)TABLE_BYTES) : "memory");
        asm volatile(
            "cp.async.bulk.shared::cta.global.mbarrier::complete_tx::bytes [%0], [%1], %2, [%3];"
            :: "r"(tab_a), "l"((const void*)g_d_h),
               "r"((uint32_t)TABLE_BYTES), "r"(mbar) : "memory");
    }

    // Wait table 2 (phase parity 1)
    asm volatile(
        "{\n\t.reg .pred P;\n\t"
        "W1_%=:\n\t"
        "mbarrier.try_wait.parity.acquire.cta.shared::cta.b64 P, [%0], 1, 0x989680;\n\t"
        "@!P bra W1_%=;\n\t}"
        :: "r"(mbar) : "memory");

    #pragma unroll
    for (int k = 0; k < EPT; k++) {
        int e = gtid + k * stride;
        if (e < n_edges) {
            float logit = part[k] + __half2float(tab[di[k]]);
            __stcs(out + e, sigmoidf_fast(logit));
        }
    }
}

extern "C" void kernel_launch(void* const* d_in, const int* in_sizes, int n_in,
                              void* d_out, int out_size) {
    const float* x   = (const float*)d_in[0];
    const int*   src = (const int*)d_in[1];
    const int*   dst = (const int*)d_in[2];
    const float* W   = (const float*)d_in[3];
    const float* b   = (const float*)d_in[4];
    float*       out = (float*)d_out;

    int n_nodes = in_sizes[0] / D;
    int n_edges = in_sizes[1];

    // Kernel 1: 8 nodes per warp, 8 warps/block -> 64 nodes/block
    {
        int nodes_per_block = 8 * 8;
        int blocks = (n_nodes + nodes_per_block - 1) / nodes_per_block;
        node_dots_kernel<<<blocks, 256>>>((const float4*)x, W, b, n_nodes);
    }
    // Kernel 2: table-swap edge scoring (grid ~140, single wave)
    {
        static bool attr_set = false;
        if (!attr_set) {
            cudaFuncSetAttribute(edge_score_swap_kernel,
                                 cudaFuncAttributeMaxDynamicSharedMemorySize,
                                 SMEM_TOTAL);
            attr_set = true;
        }
        long long per_blk = (long long)EBLK * EPT;
        int blocks = (int)((n_edges + per_blk - 1) / per_blk);  // 140 for 1e6
        edge_score_swap_kernel<<<blocks, EBLK, SMEM_TOTAL>>>(src, dst, out, n_edges);
    }
}